// round 12
// baseline (speedup 1.0000x reference)
#include <cuda_runtime.h>
#include <cstdint>

#define D_DIM 64
#define BT 64            // b per block
#define NT 32            // n per block
#define TPB 256
#define XS 68            // x-transpose row stride (floats): 272B = 17x16B, 16B-aligned, conflict-spread
#define AS 68            // a/b-dup row stride (floats)

// ---- packed f32x2 helpers (Blackwell FFMA2 path) ----
__device__ __forceinline__ uint64_t pk2(float lo, float hi) {
    uint64_t r; asm("mov.b64 %0, {%1, %2};" : "=l"(r) : "f"(lo), "f"(hi)); return r;
}
__device__ __forceinline__ void upk2(uint64_t v, float& lo, float& hi) {
    asm("mov.b64 {%0, %1}, %2;" : "=f"(lo), "=f"(hi) : "l"(v));
}
__device__ __forceinline__ uint64_t fma2(uint64_t a, uint64_t b, uint64_t c) {
    uint64_t d; asm("fma.rn.f32x2 %0, %1, %2, %3;" : "=l"(d) : "l"(a), "l"(b), "l"(c)); return d;
}
__device__ __forceinline__ uint64_t mul2(uint64_t a, uint64_t b) {
    uint64_t d; asm("mul.rn.f32x2 %0, %1, %2;" : "=l"(d) : "l"(a), "l"(b)); return d;
}
__device__ __forceinline__ uint64_t add2(uint64_t a, uint64_t b) {
    uint64_t d; asm("add.rn.f32x2 %0, %1, %2;" : "=l"(d) : "l"(a), "l"(b)); return d;
}

extern __shared__ float smem_dyn[];

__global__ __launch_bounds__(TPB, 4)
void wavelet_kernel(const float* __restrict__ x,
                    const float* __restrict__ centers,
                    const float* __restrict__ scales,
                    float* __restrict__ out, int N)
{
    float* sx  = smem_dyn;                  // [64 d][XS]: x transposed to [d][b]
    float* sad = sx  + D_DIM * XS;          // [64 d][AS]: (1/s, 1/s) dup pairs over n
    float* sbd = sad + D_DIM * AS;          // [64 d][AS]: (-c/s, -c/s) dup pairs

    const int tid = threadIdx.x;
    const int b0 = blockIdx.x * BT;
    const int n0 = blockIdx.y * NT;

    // x tile: read coalesced (b-row major), store transposed [d][b]
    #pragma unroll 4
    for (int i = tid; i < BT * D_DIM; i += TPB) {
        int r = i >> 6, c = i & 63;                 // r = b-local, c = d
        sx[c * XS + r] = x[(b0 + r) * D_DIM + c];
    }
    // a/b tiles: read coalesced, store duplicated pairs at [d][2n..2n+1]
    #pragma unroll 4
    for (int i = tid; i < NT * D_DIM; i += TPB) {
        int n = i >> 6, d = i & 63;
        int g = (n0 + n) * D_DIM + d;
        float inv = 1.0f / scales[g];
        float bb  = -centers[g] * inv;
        *reinterpret_cast<float2*>(&sad[d * AS + 2 * n]) = make_float2(inv, inv);
        *reinterpret_cast<float2*>(&sbd[d * AS + 2 * n]) = make_float2(bb, bb);
    }
    __syncthreads();

    const int bg = tid & 15;   // 4 b's at 4*bg (2 packed b-pairs)
    const int ng = tid >> 4;   // 2 n's at 2*ng

    const float* xcol = sx  + 4 * bg;
    const float* acol = sad + 4 * ng;
    const float* bcol = sbd + 4 * ng;

    const uint64_t M1 = pk2(-1.0f, -1.0f);
    // all-packed accumulators: lanes = (b, b+1); [bp][nl]
    uint64_t p[2][2], s[2][2];
    #pragma unroll
    for (int bp = 0; bp < 2; bp++)
        #pragma unroll
        for (int nl = 0; nl < 2; nl++) { p[bp][nl] = pk2(1.f, 1.f); s[bp][nl] = pk2(0.f, 0.f); }

    #pragma unroll
    for (int half = 0; half < 2; half++) {
        #pragma unroll 1
        for (int q = 0; q < 8; q++) {
            const int d0 = half * 32 + q * 4;
            #pragma unroll
            for (int dd = 0; dd < 4; dd++) {
                const int d = d0 + dd;
                const ulonglong2 xv = *reinterpret_cast<const ulonglong2*>(xcol + d * XS);
                const ulonglong2 av = *reinterpret_cast<const ulonglong2*>(acol + d * AS);
                const ulonglong2 bv = *reinterpret_cast<const ulonglong2*>(bcol + d * AS);
                const uint64_t xp[2] = {xv.x, xv.y};
                const uint64_t A[2]  = {av.x, av.y};
                const uint64_t Bv[2] = {bv.x, bv.y};
                #pragma unroll
                for (int bp = 0; bp < 2; bp++) {
                    #pragma unroll
                    for (int nl = 0; nl < 2; nl++) {
                        uint64_t z = fma2(xp[bp], A[nl], Bv[nl]);
                        uint64_t w = fma2(z, z, M1);       // z^2 - 1
                        s[bp][nl] = add2(s[bp][nl], w);    // packed sum (lanes = distinct b)
                        p[bp][nl] = mul2(p[bp][nl], w);    // packed product
                    }
                }
            }
        }

        if (half == 0) {
            // range-control fold: Gaussian factor for first 32 dims (per lane)
            #pragma unroll
            for (int bp = 0; bp < 2; bp++)
                #pragma unroll
                for (int nl = 0; nl < 2; nl++) {
                    float p0, p1, s0, s1;
                    upk2(p[bp][nl], p0, p1);
                    upk2(s[bp][nl], s0, s1);
                    p0 *= __expf(-0.5f * (s0 + 32.0f));
                    p1 *= __expf(-0.5f * (s1 + 32.0f));
                    p[bp][nl] = pk2(p0, p1);
                    s[bp][nl] = pk2(0.f, 0.f);
                }
        }
    }

    // epilogue: lanes are (b, b+1); store float2 over the 2 n's per b-row
    #pragma unroll
    for (int bp = 0; bp < 2; bp++) {
        float h0[2], h1[2];   // [nl] for lane0 (b=4bg+2bp) and lane1 (b=+1)
        #pragma unroll
        for (int nl = 0; nl < 2; nl++) {
            float p0, p1, s0, s1;
            upk2(p[bp][nl], p0, p1);
            upk2(s[bp][nl], s0, s1);
            h0[nl] = p0 * __expf(-0.5f * (s0 + 32.0f));
            h1[nl] = p1 * __expf(-0.5f * (s1 + 32.0f));
        }
        const long r0 = (long)(b0 + 4 * bg + 2 * bp) * N + n0 + 2 * ng;
        *reinterpret_cast<float2*>(out + r0)     = make_float2(h0[0], h0[1]);
        *reinterpret_cast<float2*>(out + r0 + N) = make_float2(h1[0], h1[1]);
    }
}

extern "C" void kernel_launch(void* const* d_in, const int* in_sizes, int n_in,
                              void* d_out, int out_size)
{
    const float* x       = (const float*)d_in[0];
    const float* centers = (const float*)d_in[1];
    const float* scales  = (const float*)d_in[2];
    float* out = (float*)d_out;

    const int B = in_sizes[0] / D_DIM;   // 8192
    const int N = in_sizes[1] / D_DIM;   // 512

    const int smem_bytes = (D_DIM * XS + 2 * D_DIM * AS) * sizeof(float); // 52224
    static bool attr_set = false;
    if (!attr_set) {
        cudaFuncSetAttribute(wavelet_kernel,
                             cudaFuncAttributeMaxDynamicSharedMemorySize, smem_bytes);
        attr_set = true;
    }

    dim3 grid(B / BT, N / NT);           // (128, 16) = 2048 blocks
    wavelet_kernel<<<grid, TPB, smem_bytes>>>(x, centers, scales, out, N);
}

// round 13
// speedup vs baseline: 1.1325x; 1.1325x over previous
#include <cuda_runtime.h>
#include <cstdint>

#define D_DIM 64
#define BT 64            // b per block
#define NT 64            // n per block
#define TPB 256
#define XSTRIDE 68       // floats; 16B-aligned row stride, conflict-free
#define ASTRIDE 68

// ---- packed f32x2 helpers (Blackwell FFMA2 path) ----
__device__ __forceinline__ uint64_t pk2(float lo, float hi) {
    uint64_t r; asm("mov.b64 %0, {%1, %2};" : "=l"(r) : "f"(lo), "f"(hi)); return r;
}
__device__ __forceinline__ void upk2(uint64_t v, float& lo, float& hi) {
    asm("mov.b64 {%0, %1}, %2;" : "=f"(lo), "=f"(hi) : "l"(v));
}
__device__ __forceinline__ uint64_t fma2(uint64_t a, uint64_t b, uint64_t c) {
    uint64_t d; asm("fma.rn.f32x2 %0, %1, %2, %3;" : "=l"(d) : "l"(a), "l"(b), "l"(c)); return d;
}
__device__ __forceinline__ uint64_t mul2(uint64_t a, uint64_t b) {
    uint64_t d; asm("mul.rn.f32x2 %0, %1, %2;" : "=l"(d) : "l"(a), "l"(b)); return d;
}

extern __shared__ float smem_dyn[];

// One 4-dim block: 4 b x 4 n per thread (2 packed n-pairs). R8 body, dblk dynamic.
__device__ __forceinline__ void do_dblk(const float* __restrict__ xrow,
                                        const float* __restrict__ arow,
                                        const float* __restrict__ brow,
                                        int dblk, uint64_t M1,
                                        float (&s0)[4][2], float (&s1)[4][2],
                                        uint64_t (&pacc)[4][2])
{
    float xq[4][4];
    #pragma unroll
    for (int bi = 0; bi < 4; bi++) {
        float4 v = *reinterpret_cast<const float4*>(xrow + bi * XSTRIDE + dblk);
        xq[bi][0] = v.x; xq[bi][1] = v.y; xq[bi][2] = v.z; xq[bi][3] = v.w;
    }
    #pragma unroll
    for (int dd = 0; dd < 4; dd++) {
        const int off = (dblk + dd) * ASTRIDE;
        const ulonglong2 av = *reinterpret_cast<const ulonglong2*>(arow + off);
        const ulonglong2 bv = *reinterpret_cast<const ulonglong2*>(brow + off);
        const uint64_t A[2]  = {av.x, av.y};
        const uint64_t Bv[2] = {bv.x, bv.y};
        #pragma unroll
        for (int bi = 0; bi < 4; bi++) {
            const uint64_t xp = pk2(xq[bi][dd], xq[bi][dd]);
            #pragma unroll
            for (int k = 0; k < 2; k++) {
                uint64_t z = fma2(xp, A[k], Bv[k]);
                uint64_t w = fma2(z, z, M1);          // z^2 - 1
                float w0, w1;
                upk2(w, w0, w1);                      // pair-alias, no MOVs
                s0[bi][k] += w0;                      // scalar FADDs (R8 win)
                s1[bi][k] += w1;                      // sum z^2 = sum w + count
                pacc[bi][k] = mul2(pacc[bi][k], w);
            }
        }
    }
}

__global__ __launch_bounds__(TPB, 3)
void wavelet_kernel(const float* __restrict__ x,
                    const float* __restrict__ centers,
                    const float* __restrict__ scales,
                    float* __restrict__ out, int N)
{
    float* sx = smem_dyn;                   // [BT][XSTRIDE]  b-major
    float* sa = sx + BT * XSTRIDE;          // [D][ASTRIDE]   d-major: 1/s
    float* sb = sa + D_DIM * ASTRIDE;       // [D][ASTRIDE]   -c/s

    const int tid = threadIdx.x;
    const int b0 = blockIdx.x * BT;
    const int n0 = blockIdx.y * NT;

    // x tile (coalesced)
    #pragma unroll 2
    for (int i = tid; i < BT * D_DIM; i += TPB) {
        int r = i >> 6, c = i & 63;
        sx[r * XSTRIDE + c] = x[(b0 + r) * D_DIM + c];
    }
    // a/b tiles, transposed to [d][n]
    #pragma unroll 4
    for (int i = tid; i < NT * D_DIM; i += TPB) {
        int d = i & 63, n = i >> 6;
        int g = (n0 + n) * D_DIM + d;
        float inv = 1.0f / scales[g];
        sa[d * ASTRIDE + n] = inv;
        sb[d * ASTRIDE + n] = -centers[g] * inv;
    }
    __syncthreads();

    const int ng = tid & 15;   // 4 n's at ng*4
    const int bg = tid >> 4;   // 4 b's at bg*4
    const int rot = (tid >> 5) & 7;   // per-warp d-block rotation (desync)

    const float* xrow = sx + (bg * 4) * XSTRIDE;
    const float* arow = sa + ng * 4;
    const float* brow = sb + ng * 4;

    const uint64_t M1 = pk2(-1.0f, -1.0f);
    float s0[4][2], s1[4][2];
    uint64_t pacc[4][2];
    #pragma unroll
    for (int bi = 0; bi < 4; bi++)
        #pragma unroll
        for (int k = 0; k < 2; k++) {
            s0[bi][k] = 0.0f; s1[bi][k] = 0.0f;
            pacc[bi][k] = pk2(1.f, 1.f);
        }

    // first half: d = 0..31, warp-rotated block order (sum/product commute)
    #pragma unroll 2
    for (int q = 0; q < 8; q++)
        do_dblk(xrow, arow, brow, ((q + rot) & 7) * 4, M1, s0, s1, pacc);

    // range-control fold: Gaussian factor for first 32 dims
    #pragma unroll
    for (int bi = 0; bi < 4; bi++)
        #pragma unroll
        for (int k = 0; k < 2; k++) {
            float p0, p1;
            upk2(pacc[bi][k], p0, p1);
            p0 *= __expf(-0.5f * (s0[bi][k] + 32.0f));
            p1 *= __expf(-0.5f * (s1[bi][k] + 32.0f));
            pacc[bi][k] = pk2(p0, p1);
            s0[bi][k] = 0.0f; s1[bi][k] = 0.0f;
        }

    // second half: d = 32..63, rotated
    #pragma unroll 2
    for (int q = 0; q < 8; q++)
        do_dblk(xrow, arow, brow, 32 + ((q + rot) & 7) * 4, M1, s0, s1, pacc);

    // epilogue
    float* orow = out + (long)(b0 + bg * 4) * N + n0 + ng * 4;
    #pragma unroll
    for (int bi = 0; bi < 4; bi++) {
        float h[4];
        #pragma unroll
        for (int k = 0; k < 2; k++) {
            float p0, p1;
            upk2(pacc[bi][k], p0, p1);
            h[2 * k]     = p0 * __expf(-0.5f * (s0[bi][k] + 32.0f));
            h[2 * k + 1] = p1 * __expf(-0.5f * (s1[bi][k] + 32.0f));
        }
        float4 v = {h[0], h[1], h[2], h[3]};
        *reinterpret_cast<float4*>(orow + (long)bi * N) = v;
    }
}

extern "C" void kernel_launch(void* const* d_in, const int* in_sizes, int n_in,
                              void* d_out, int out_size)
{
    const float* x       = (const float*)d_in[0];
    const float* centers = (const float*)d_in[1];
    const float* scales  = (const float*)d_in[2];
    float* out = (float*)d_out;

    const int B = in_sizes[0] / D_DIM;   // 8192
    const int N = in_sizes[1] / D_DIM;   // 512

    const int smem_bytes = (BT * XSTRIDE + 2 * D_DIM * ASTRIDE) * sizeof(float); // 52224
    static bool attr_set = false;
    if (!attr_set) {
        cudaFuncSetAttribute(wavelet_kernel,
                             cudaFuncAttributeMaxDynamicSharedMemorySize, smem_bytes);
        attr_set = true;
    }

    dim3 grid(B / BT, N / NT);           // (128, 8) = 1024 blocks
    wavelet_kernel<<<grid, TPB, smem_bytes>>>(x, centers, scales, out, N);
}